// round 10
// baseline (speedup 1.0000x reference)
#include <cuda_runtime.h>
#include <cuda_bf16.h>
#include <cstddef>

// ---------------------------------------------------------------------------
// GRU (B=64, N=1024, T=512), exact fp32, packed f32x2 FMA.
//
// Phase 1:  XP = x @ [W1|W2] + [b1|b2] — BK=16 SGEMM, cp.async double buffer
//           (zero-register prefetch -> no spills at 2 CTAs/SM), W1/W2 read
//           directly (no packing pass).
// Phase 2:  ONE persistent kernel (unchanged): 128 blocks, W resident in
//           smem, transposed double-buffered h, one grid barrier per step.
// ---------------------------------------------------------------------------

#define Bsz 64
#define Nn  1024
#define Tt  512
#define N3  3072
#define Kd  1024
#define NB  128

typedef unsigned long long ull;

__device__ __forceinline__ ull pk2(float lo, float hi) {
    ull r; asm("mov.b64 %0, {%1,%2};" : "=l"(r) : "f"(lo), "f"(hi)); return r;
}
__device__ __forceinline__ void upk2(ull v, float& lo, float& hi) {
    asm("mov.b64 {%0,%1}, %2;" : "=f"(lo), "=f"(hi) : "l"(v));
}
__device__ __forceinline__ void ffma2(ull& d, ull a, ull b) {
    asm("fma.rn.f32x2 %0, %1, %2, %0;" : "+l"(d) : "l"(a), "l"(b));
}
__device__ __forceinline__ void cp16(void* s, const void* g) {
    unsigned sa = (unsigned)__cvta_generic_to_shared(s);
    asm volatile("cp.async.ca.shared.global [%0], [%1], 16;" :: "r"(sa), "l"(g));
}
__device__ __forceinline__ void cp_commit() {
    asm volatile("cp.async.commit_group;");
}
template <int N>
__device__ __forceinline__ void cp_wait() {
    asm volatile("cp.async.wait_group %0;" :: "n"(N));
}

// ------------------------- device scratch ----------------------------------
__device__ float g_XP[(size_t)Bsz * Tt * N3];    // 402 MB input projections
__device__ float g_Ht[2][(size_t)Nn * Bsz];      // h, TRANSPOSED [k][m]

__device__ volatile unsigned g_bar_gen;
__device__ unsigned g_bar_cnt;

__global__ void init_state() {
    int i = blockIdx.x * 256 + threadIdx.x;
    if (i < Nn * Bsz) g_Ht[0][i] = 0.f;
    if (i == 0) { g_bar_cnt = 0; g_bar_gen = 0; }
}

// ------------------------- phase 1: input projection ------------------------
// C[32768, 3072] = A[32768,1024] * [W1|W2] + [b1|b2]
// BM=BN=128, BK=16, 256 threads, 8x8/thread, cp.async ping-pong.
__global__ __launch_bounds__(256, 2) void xproj(
        const float* __restrict__ fx,
        const float* __restrict__ W1, const float* __restrict__ W2,
        const float* __restrict__ b1, const float* __restrict__ b2) {
    __shared__ float As[2][16][128];
    __shared__ float Bs[2][16][128];

    const int tid = threadIdx.x;
    const int jb  = blockIdx.x * 128;
    const int m0  = blockIdx.y * 128;
    const int b   = m0 >> 9;
    const int t0  = m0 & 511;
    const float* Abase = fx + ((size_t)b * Kd) * Tt + t0;

    // W source: uniform per block
    const float* Bsrc;
    size_t bstride;
    if (jb < 2048) { Bsrc = W1 + jb;        bstride = 2048; }
    else           { Bsrc = W2 + (jb - 2048); bstride = 1024; }

    const int lm = tid & 31;          // float4 lane along m / j
    const int lk = tid >> 5;          // k row 0..7 (+8)
    const int ty = tid >> 4, tx = tid & 15;

    // issue one 16-k chunk into buffer nb (4 cp.async per thread)
    auto issue = [&](int k0, int nb) {
        int k1 = k0 + lk, k2 = k0 + lk + 8;
        cp16(&As[nb][lk][lm * 4],     Abase + (size_t)k1 * Tt + lm * 4);
        cp16(&As[nb][lk + 8][lm * 4], Abase + (size_t)k2 * Tt + lm * 4);
        cp16(&Bs[nb][lk][lm * 4],     Bsrc + (size_t)k1 * bstride + lm * 4);
        cp16(&Bs[nb][lk + 8][lm * 4], Bsrc + (size_t)k2 * bstride + lm * 4);
        cp_commit();
    };

    ull acc[8][4];
#pragma unroll
    for (int r = 0; r < 8; r++)
#pragma unroll
        for (int c = 0; c < 4; c++) acc[r][c] = 0ull;

    issue(0, 0);
    int buf = 0;
    for (int k0 = 0; k0 < Kd; k0 += 16) {
        const bool more = (k0 + 16 < Kd);
        if (more) { issue(k0 + 16, buf ^ 1); cp_wait<1>(); }
        else      { cp_wait<0>(); }
        __syncthreads();

#pragma unroll
        for (int q = 0; q < 16; q++) {
            const float4 a0 = *(const float4*)&As[buf][q][ty * 8];
            const float4 a1 = *(const float4*)&As[buf][q][ty * 8 + 4];
            const ull* bv = (const ull*)&Bs[buf][q][tx * 8];
            const ull b0 = bv[0], b1v = bv[1], b2v = bv[2], b3v = bv[3];
            float arow[8] = {a0.x, a0.y, a0.z, a0.w, a1.x, a1.y, a1.z, a1.w};
#pragma unroll
            for (int r = 0; r < 8; r++) {
                ull aa = pk2(arow[r], arow[r]);
                ffma2(acc[r][0], aa, b0);
                ffma2(acc[r][1], aa, b1v);
                ffma2(acc[r][2], aa, b2v);
                ffma2(acc[r][3], aa, b3v);
            }
        }
        __syncthreads();
        buf ^= 1;
    }

    float bb[8];
#pragma unroll
    for (int c = 0; c < 8; c++) {
        int j = jb + tx * 8 + c;
        bb[c] = (j < 2048) ? b1[j] : b2[j - 2048];
    }

#pragma unroll
    for (int r = 0; r < 8; r++) {
        float* op = g_XP + (size_t)(m0 + ty * 8 + r) * N3 + jb + tx * 8;
        float4 v0, v1;
        upk2(acc[r][0], v0.x, v0.y); upk2(acc[r][1], v0.z, v0.w);
        upk2(acc[r][2], v1.x, v1.y); upk2(acc[r][3], v1.z, v1.w);
        v0.x += bb[0]; v0.y += bb[1]; v0.z += bb[2]; v0.w += bb[3];
        v1.x += bb[4]; v1.y += bb[5]; v1.z += bb[6]; v1.w += bb[7];
        *(float4*)&op[0] = v0;
        *(float4*)&op[4] = v1;
    }
}

// ------------------------- phase 2: persistent recurrence (unchanged) -------
#define SM_W   (1024 * 24)
#define SM_HT  (4 * 64 * 64)
#define SM_P   (4 * 64 * 26)
#define SM_TOT ((SM_W + SM_HT + SM_P + 24) * 4)

__device__ __forceinline__ void grid_sync() {
    __syncthreads();
    if (threadIdx.x == 0) {
        unsigned gen = g_bar_gen;
        __threadfence();
        if (atomicAdd(&g_bar_cnt, 1u) == NB - 1) {
            g_bar_cnt = 0;
            __threadfence();
            g_bar_gen = gen + 1;
        } else {
            while (g_bar_gen == gen) { __nanosleep(64); }
        }
        __threadfence();
    }
    __syncthreads();
}

__global__ __launch_bounds__(256, 1) void recurrence(
        const float* __restrict__ W1, const float* __restrict__ W2,
        const float* __restrict__ b1, const float* __restrict__ b2,
        float* __restrict__ out) {
    extern __shared__ float smem[];
    float* w_s    = smem;                 // [k][24]
    float* hT_s   = w_s + SM_W;           // [g][64][64]
    float* p_s    = hT_s + SM_HT;         // [g][64][26]
    float* bias_s = p_s + SM_P;           // [24]

    const int tid = threadIdx.x;
    const int blk = blockIdx.x;
    const int gc0 = blk * 8;
    const int grp = tid >> 6;
    const int gt  = tid & 63;
    const int rowg = gt >> 2;
    const int cg   = gt & 3;

#pragma unroll
    for (int j = 0; j < 24; j++) {
        int l = tid + j * 256;
        int k = l / 6, f = l - k * 6;
        int p = f >> 1, half = f & 1;
        const float* src = (p == 0) ? (W1 + (size_t)k * 2048 + gc0 + half * 4)
                         : (p == 1) ? (W1 + (size_t)k * 2048 + 1024 + gc0 + half * 4)
                                    : (W2 + (size_t)k * 1024 + gc0 + half * 4);
        *(float4*)&w_s[k * 24 + p * 8 + half * 4] = *(const float4*)src;
    }
    if (tid < 24) {
        int p = tid >> 3, ii = tid & 7, n = gc0 + ii;
        bias_s[tid] = (p == 0) ? b1[n] : (p == 1) ? b1[1024 + n] : b2[n];
    }
    __syncthreads();

    for (int t = 0; t < Tt; t++) {
        const float* hcur = g_Ht[t & 1];
        float*       hnxt = g_Ht[(t + 1) & 1];

        float xq[2][3], hp[2];
#pragma unroll
        for (int e = 0; e < 2; e++) {
            int idx = tid + e * 256;
            int m = idx & 63, i = idx >> 6;
            int n = gc0 + i;
            const float* xp = g_XP + ((size_t)(m * Tt + t)) * N3 + n;
            xq[e][0] = xp[0];
            xq[e][1] = xp[1024];
            xq[e][2] = xp[2048];
            hp[e]    = hcur[n * 64 + m];
        }

        ull acc[4][3];
#pragma unroll
        for (int i = 0; i < 4; i++) { acc[i][0] = 0; acc[i][1] = 0; acc[i][2] = 0; }

        for (int it = 0; it < 4; it++) {
#pragma unroll
            for (int j = 0; j < 16; j++) {
                int l = tid + j * 256;
                int m4 = l & 15, kl = (l >> 4) & 63, g = l >> 10;
                *(float4*)&hT_s[(g * 64 + kl) * 64 + m4 * 4] =
                    *(const float4*)&hcur[(g * 256 + it * 64 + kl) * 64 + m4 * 4];
            }
            __syncthreads();

            const float* hg = hT_s + grp * (64 * 64);
            const float* wb = w_s + (grp * 256 + it * 64) * 24;
#pragma unroll 8
            for (int kk = 0; kk < 64; kk++) {
                float4 hv = *(const float4*)&hg[kk * 64 + rowg * 4];
                const ull* wv = (const ull*)&wb[kk * 24 + cg * 6];
                const ull w0 = wv[0], w1 = wv[1], w2 = wv[2];
                float arv[4] = {hv.x, hv.y, hv.z, hv.w};
#pragma unroll
                for (int i = 0; i < 4; i++) {
                    ull aa = pk2(arv[i], arv[i]);
                    ffma2(acc[i][0], aa, w0);
                    ffma2(acc[i][1], aa, w1);
                    ffma2(acc[i][2], aa, w2);
                }
            }
            __syncthreads();
        }

#pragma unroll
        for (int i = 0; i < 4; i++) {
            ull* pp = (ull*)&p_s[(grp * 64 + rowg * 4 + i) * 26 + cg * 6];
            pp[0] = acc[i][0]; pp[1] = acc[i][1]; pp[2] = acc[i][2];
        }
        __syncthreads();

#pragma unroll
        for (int e = 0; e < 2; e++) {
            int idx = tid + e * 256;
            int m = idx & 63, i = idx >> 6;
            int n = gc0 + i;
            float s1 = 0.f, s2 = 0.f, sh = 0.f;
#pragma unroll
            for (int g = 0; g < 4; g++) {
                const float* pp = &p_s[(g * 64 + m) * 26];
                s1 += pp[i]; s2 += pp[8 + i]; sh += pp[16 + i];
            }
            float z = 1.f / (1.f + expf(-(xq[e][0] + s1 + bias_s[i])));
            float r = 1.f / (1.f + expf(-(xq[e][1] + s2 + bias_s[8 + i])));
            float hrec = sh + bias_s[16 + i];
            float hn = z * hp[e] + (1.f - z) * tanhf(xq[e][2] + r * hrec);
            hnxt[n * 64 + m] = hn;
            if (t == Tt - 1) out[m * Nn + n] = hn;
        }

        __threadfence();
        grid_sync();
    }
}

// ---------------------------------------------------------------------------
extern "C" void kernel_launch(void* const* d_in, const int* in_sizes, int n_in,
                              void* d_out, int out_size) {
    const float *fx = nullptr, *W1 = nullptr, *b1 = nullptr, *W2 = nullptr, *b2 = nullptr;
    for (int i = 0; i < n_in; i++) {
        switch (in_sizes[i]) {
            case Bsz * Nn * Tt:  fx = (const float*)d_in[i]; break;
            case Nn * 2 * Nn:    W1 = (const float*)d_in[i]; break;
            case 2 * Nn:         b1 = (const float*)d_in[i]; break;
            case Nn * Nn:        W2 = (const float*)d_in[i]; break;
            case Nn:             b2 = (const float*)d_in[i]; break;
            default: break;
        }
    }
    float* out = (float*)d_out;

    static int smem_set = 0;
    if (!smem_set) {
        cudaFuncSetAttribute(recurrence, cudaFuncAttributeMaxDynamicSharedMemorySize,
                             SM_TOT);
        smem_set = 1;
    }

    init_state<<<(Nn * Bsz + 255) / 256, 256>>>();

    dim3 g1(N3 / 128, (Bsz * Tt) / 128);   // (24, 256)
    xproj<<<g1, 256>>>(fx, W1, W2, b1, b2);

    recurrence<<<NB, 256, SM_TOT>>>(W1, W2, b1, b2, out);
}